// round 7
// baseline (speedup 1.0000x reference)
#include <cuda_runtime.h>
#include <cuda_bf16.h>

typedef unsigned long long ull;

#define NCTAS 147
#define NT    512
#define ROWS  28          // rows per CTA (last CTA partially valid)
#define NPAIR 7           // row pairs per thread (half of 14 rows)
#define RS    32          // padded row stride (floats); halves 16B-aligned
#define HH    256
#define EE    64
#define VV    64
#define ZZ    128
#define TS    119
#define BTOT  4096

// Pre-duplicated weights for packed f32x2 math.
// wrz[k][j] = (w_r,w_r,w_z,w_z) ; wn[k][j] = (w_n,w_n)
// k-slot bases: L0 wi:0(K=64) wh:64 | L1 wi:320 wh:576 | L2 wi:832 wh:1088
__device__ ulonglong2 g_wrz[1344 * 256];
__device__ ull        g_wn [1344 * 256];
__device__ ulonglong2 g_zrz[128 * 256];   // z2h rows (j, 256+j) duplicated
__device__ ull        g_zn [128 * 256];   // z2h row (512+j) duplicated
__device__ float2     g_ow [256 * 64];    // out_w transposed + duplicated: [k][v]

struct SM {
    float hb[3][HH][RS];        // hidden state, k-major, slot-mapped   98,304 B
    float xz[ZZ][RS];           // z at init / embedding per step       16,384 B
    float br[3][HH];            // b_ih_r + b_hh_r
    float bz[3][HH];            // b_ih_z + b_hh_z
    float bin_[3][HH];          // b_ih_n
    float bhn_[3][HH];          // b_hh_n                               12,288 B
    float lbuf[ROWS][VV + 1];   // logits for argmax                     7,280 B
    int   tok[ROWS];
};

__device__ __forceinline__ int slotof(int r) { return r + (r >= 14 ? 2 : 0); }

// ---------------- packed f32x2 helpers ----------------
__device__ __forceinline__ ull dupbits(float f) {
    unsigned u = __float_as_uint(f);
    return ((ull)u << 32) | u;
}
__device__ __forceinline__ ull dup2(float v) {
    ull r; asm("mov.b64 %0, {%1, %1};" : "=l"(r) : "f"(v)); return r;
}
__device__ __forceinline__ void fma2(ull& d, ull a, ull b) {
    asm("fma.rn.f32x2 %0, %1, %2, %0;" : "+l"(d) : "l"(a), "l"(b));
}
__device__ __forceinline__ float f2lo(ull v) { return __uint_as_float((unsigned)(v & 0xffffffffULL)); }
__device__ __forceinline__ float f2hi(ull v) { return __uint_as_float((unsigned)(v >> 32)); }

// ---------------- flag-proof ~1ulp activations ----------------
__device__ __forceinline__ float exp_acc(float x) {
    x = fminf(fmaxf(x, -87.0f), 87.0f);
    float n = rintf(x * 1.4426950408889634f);
    float r = fmaf(n, -6.93145752e-01f, x);
    r = fmaf(n, -1.42860677e-06f, r);
    float p = 1.98412698412e-4f;
    p = fmaf(p, r, 1.38888888889e-3f);
    p = fmaf(p, r, 8.33333333333e-3f);
    p = fmaf(p, r, 4.16666666667e-2f);
    p = fmaf(p, r, 1.66666666667e-1f);
    p = fmaf(p, r, 0.5f);
    p = fmaf(p, r, 1.0f);
    p = fmaf(p, r, 1.0f);
    float sc = __int_as_float(((int)n + 127) << 23);
    return p * sc;
}
__device__ __forceinline__ float sigm(float x) {
    float e = exp_acc(-x);
    return __fdiv_rn(1.0f, 1.0f + e);
}
__device__ __forceinline__ float mytanh(float x) {
    float a = fabsf(x);
    float e = exp_acc(-2.0f * a);
    float r = __fdiv_rn(1.0f - e, 1.0f + e);
    return copysignf(r, x);
}

// ---------------- prep kernel: transpose + duplicate weights ----------------
__global__ void prep_kernel(
    const float* __restrict__ wi0, const float* __restrict__ wh0,
    const float* __restrict__ wi1, const float* __restrict__ wh1,
    const float* __restrict__ wi2, const float* __restrict__ wh2,
    const float* __restrict__ z2h_w, const float* __restrict__ out_w)
{
    int bx = blockIdx.x;
    int j = threadIdx.x;
    if (bx < 1344) {
        const float* W; int ld, kk;
        if      (bx <   64) { W = wi0; ld =  64; kk = bx;        }
        else if (bx <  320) { W = wh0; ld = 256; kk = bx -   64; }
        else if (bx <  576) { W = wi1; ld = 256; kk = bx -  320; }
        else if (bx <  832) { W = wh1; ld = 256; kk = bx -  576; }
        else if (bx < 1088) { W = wi2; ld = 256; kk = bx -  832; }
        else                { W = wh2; ld = 256; kk = bx - 1088; }
        float wr = W[(size_t)j * ld + kk];
        float wz = W[(size_t)(256 + j) * ld + kk];
        float wn = W[(size_t)(512 + j) * ld + kk];
        ulonglong2 e; e.x = dupbits(wr); e.y = dupbits(wz);
        g_wrz[bx * 256 + j] = e;
        g_wn [bx * 256 + j] = dupbits(wn);
    } else if (bx < 1472) {
        int kz = bx - 1344;
        float a = z2h_w[(size_t)j * ZZ + kz];
        float b = z2h_w[(size_t)(256 + j) * ZZ + kz];
        float c = z2h_w[(size_t)(512 + j) * ZZ + kz];
        ulonglong2 e; e.x = dupbits(a); e.y = dupbits(b);
        g_zrz[kz * 256 + j] = e;
        g_zn [kz * 256 + j] = dupbits(c);
    } else {
        int m = bx - 1472;                 // 0..63
        int id = m * 256 + j;
        int k = id >> 6, v = id & 63;
        float w = out_w[(size_t)v * HH + k];
        g_ow[k * 64 + v] = make_float2(w, w);
    }
}

// ---------------- GEMM phase: thread owns gate j, 7 row-pairs ----------------
// acc sections: (0,1,SN) <- (r, z, n)
template<int K, int SN>
__device__ __forceinline__ void gemm_phase(const ulonglong2* __restrict__ wrz,
                                           const ull* __restrict__ wn,
                                           const float* __restrict__ xb,
                                           ull (&acc)[4][NPAIR], int j)
{
    const ulonglong2* wp = wrz + j;
    const ull*        np = wn  + j;
    ulonglong2 w0 = wp[0], w1 = wp[256];
    ull        n0 = np[0], n1 = np[256];
    const ulonglong2* wpp = wp + 512;
    const ull*        npp = np + 512;
#pragma unroll 2
    for (int k = 0; k < K; k++) {
        ulonglong2 wc = w0; w0 = w1;
        ull        nc = n0; n0 = n1;
        if (k + 2 < K) { w1 = wpp[0]; n1 = npp[0]; }
        wpp += 256; npp += 256;
        const ulonglong2* xq = (const ulonglong2*)(xb + (size_t)k * RS);
        ulonglong2 xa = xq[0], xb2 = xq[1], xc = xq[2];
        ull x6 = ((const ull*)(xq + 3))[0];
        ull wr = wc.x, wz = wc.y;
        fma2(acc[0][0], wr, xa.x);  fma2(acc[0][1], wr, xa.y);
        fma2(acc[0][2], wr, xb2.x); fma2(acc[0][3], wr, xb2.y);
        fma2(acc[0][4], wr, xc.x);  fma2(acc[0][5], wr, xc.y);
        fma2(acc[0][6], wr, x6);
        fma2(acc[1][0], wz, xa.x);  fma2(acc[1][1], wz, xa.y);
        fma2(acc[1][2], wz, xb2.x); fma2(acc[1][3], wz, xb2.y);
        fma2(acc[1][4], wz, xc.x);  fma2(acc[1][5], wz, xc.y);
        fma2(acc[1][6], wz, x6);
        fma2(acc[SN][0], nc, xa.x);  fma2(acc[SN][1], nc, xa.y);
        fma2(acc[SN][2], nc, xb2.x); fma2(acc[SN][3], nc, xb2.y);
        fma2(acc[SN][4], nc, xc.x);  fma2(acc[SN][5], nc, xc.y);
        fma2(acc[SN][6], nc, x6);
    }
}

// One GRU layer step for layer l (single-buffer, in-place update).
template<int KIN>
__device__ __forceinline__ void layer_stepB(SM* s, const float* __restrict__ xb,
                                            const ulonglong2* __restrict__ wrzI,
                                            const ull* __restrict__ wnI,
                                            const ulonglong2* __restrict__ wrzH,
                                            const ull* __restrict__ wnH,
                                            int l, int j, int ro)
{
    ull acc[4][NPAIR];
    {
        ull b0 = dup2(s->br[l][j]);
        ull b1 = dup2(s->bz[l][j]);
        ull b2 = dup2(s->bin_[l][j]);
        ull b3 = dup2(s->bhn_[l][j]);
#pragma unroll
        for (int p = 0; p < NPAIR; p++) {
            acc[0][p] = b0; acc[1][p] = b1; acc[2][p] = b2; acc[3][p] = b3;
        }
    }
    gemm_phase<KIN, 2>(wrzI, wnI, xb,                acc, j);   // x @ wi^T -> r, z, inn
    gemm_phase<HH,  3>(wrzH, wnH, &s->hb[l][0][ro],  acc, j);   // h @ wh^T -> r, z, hn
    __syncthreads();                        // all reads of hb[l] done
    float* hrow = &s->hb[l][j][ro];
#pragma unroll
    for (int p = 0; p < NPAIR; p++) {
        float2 hold = *(const float2*)(hrow + 2 * p);
        float rlo = sigm(f2lo(acc[0][p])), rhi = sigm(f2hi(acc[0][p]));
        float ulo = sigm(f2lo(acc[1][p])), uhi = sigm(f2hi(acc[1][p]));
        float nlo = mytanh(f2lo(acc[2][p]) + rlo * f2lo(acc[3][p]));
        float nhi = mytanh(f2hi(acc[2][p]) + rhi * f2hi(acc[3][p]));
        float2 hnew;
        hnew.x = (1.0f - ulo) * nlo + ulo * hold.x;
        hnew.y = (1.0f - uhi) * nhi + uhi * hold.y;
        *(float2*)(hrow + 2 * p) = hnew;
    }
    __syncthreads();                        // new hb[l] visible
}

__global__ void __launch_bounds__(NT, 1) moldec_kernel(
    const float* __restrict__ z,     const float* __restrict__ emb,
    const float* __restrict__ z2h_b, const float* __restrict__ out_b,
    const float* __restrict__ bi0, const float* __restrict__ bh0,
    const float* __restrict__ bi1, const float* __restrict__ bh1,
    const float* __restrict__ bi2, const float* __restrict__ bh2,
    float* __restrict__ out)
{
    extern __shared__ char smraw[];
    SM* s = (SM*)smraw;
    const int tid = threadIdx.x;
    const int row0 = blockIdx.x * ROWS;
    const int j  = tid & 255;      // gate index
    const int rh = tid >> 8;       // row half
    const int ro = rh * 16;        // slot offset of this half

    // combined biases to smem
    {
        const float* bip[3] = {bi0, bi1, bi2};
        const float* bhp[3] = {bh0, bh1, bh2};
        for (int i = tid; i < 3 * HH; i += NT) {
            int l = i >> 8, jj = i & 255;
            s->br[l][jj]   = bip[l][jj]          + bhp[l][jj];
            s->bz[l][jj]   = bip[l][HH + jj]     + bhp[l][HH + jj];
            s->bin_[l][jj] = bip[l][2 * HH + jj];
            s->bhn_[l][jj] = bhp[l][2 * HH + jj];
        }
    }
    // stage z transposed (k-major, slot-mapped), zero-fill invalid rows
    for (int i = tid; i < ZZ * ROWS; i += NT) {
        int r = i >> 7, k = i & 127;
        int grow = row0 + r;
        s->xz[k][slotof(r)] = (grow < BTOT) ? z[(size_t)grow * ZZ + k] : 0.0f;
    }
    if (tid < ROWS) s->tok[tid] = 1;
    __syncthreads();

    // initial hidden: h0[l] = tanh(z @ z2h_w^T + z2h_b)
    {
        ull acc[4][NPAIR];
#pragma unroll
        for (int ss = 0; ss < 3; ss++) {
            ull b = dup2(z2h_b[ss * 256 + j]);
#pragma unroll
            for (int p = 0; p < NPAIR; p++) acc[ss][p] = b;
        }
#pragma unroll
        for (int p = 0; p < NPAIR; p++) acc[3][p] = 0ULL;
        gemm_phase<ZZ, 2>(g_zrz, g_zn, &s->xz[0][ro], acc, j);
#pragma unroll
        for (int ss = 0; ss < 3; ss++) {
            float* hrow = &s->hb[ss][j][ro];
#pragma unroll
            for (int p = 0; p < NPAIR; p++) {
                float2 hv;
                hv.x = mytanh(f2lo(acc[ss][p]));
                hv.y = mytanh(f2hi(acc[ss][p]));
                *(float2*)(hrow + 2 * p) = hv;
            }
        }
        __syncthreads();
    }

    const ulonglong2* wrzi0 = g_wrz;              const ull* wni0 = g_wn;
    const ulonglong2* wrzh0 = g_wrz +   64 * 256; const ull* wnh0 = g_wn +   64 * 256;
    const ulonglong2* wrzi1 = g_wrz +  320 * 256; const ull* wni1 = g_wn +  320 * 256;
    const ulonglong2* wrzh1 = g_wrz +  576 * 256; const ull* wnh1 = g_wn +  576 * 256;
    const ulonglong2* wrzi2 = g_wrz +  832 * 256; const ull* wni2 = g_wn +  832 * 256;
    const ulonglong2* wrzh2 = g_wrz + 1088 * 256; const ull* wnh2 = g_wn + 1088 * 256;

    // out-proj thread mapping
    const int v = tid & 63;
    const int g = tid >> 6;
    const int gval = (g < 7);
    const int so0 = gval ? slotof(g * 4)     : 0;
    const int so1 = gval ? slotof(g * 4 + 2) : 0;
    const float ob = out_b[v];

    // decode loop
    for (int t = 0; t < TS; t++) {
        // embedding gather into xz (k-major, slot-mapped)
        for (int i = tid; i < EE * ROWS; i += NT) {
            int r = i >> 6, k = i & 63;
            s->xz[k][slotof(r)] = emb[(size_t)s->tok[r] * EE + k];
        }
        __syncthreads();

        layer_stepB<EE>(s, &s->xz[0][ro],    wrzi0, wni0, wrzh0, wnh0, 0, j, ro);
        layer_stepB<HH>(s, &s->hb[0][0][ro], wrzi1, wni1, wrzh1, wnh1, 1, j, ro);
        layer_stepB<HH>(s, &s->hb[1][0][ro], wrzi2, wni2, wrzh2, wnh2, 2, j, ro);

        // output projection: logits = hb[2] @ out_w^T + out_b
        {
            ull o0 = dup2(ob);
            ull o1 = o0;
            const float* xs = &s->hb[2][0][0];
            const ull* owp = (const ull*)g_ow;
            for (int kb = 0; kb < HH; kb += 8) {
                ull wreg[8];
#pragma unroll
                for (int i = 0; i < 8; i++) wreg[i] = owp[(kb + i) * 64 + v];
#pragma unroll
                for (int i = 0; i < 8; i++) {
                    const float* xrow = xs + (size_t)(kb + i) * RS;
                    fma2(o0, wreg[i], *(const ull*)(xrow + so0));
                    fma2(o1, wreg[i], *(const ull*)(xrow + so1));
                }
            }
            if (gval) {
                int r0 = g * 4;
                float l0 = f2lo(o0), l1 = f2hi(o0), l2 = f2lo(o1), l3 = f2hi(o1);
                s->lbuf[r0 + 0][v] = l0;
                s->lbuf[r0 + 1][v] = l1;
                s->lbuf[r0 + 2][v] = l2;
                s->lbuf[r0 + 3][v] = l3;
                if (row0 + r0 + 0 < BTOT) out[((size_t)(row0 + r0 + 0) * TS + t) * VV + v] = l0;
                if (row0 + r0 + 1 < BTOT) out[((size_t)(row0 + r0 + 1) * TS + t) * VV + v] = l1;
                if (row0 + r0 + 2 < BTOT) out[((size_t)(row0 + r0 + 2) * TS + t) * VV + v] = l2;
                if (row0 + r0 + 3 < BTOT) out[((size_t)(row0 + r0 + 3) * TS + t) * VV + v] = l3;
            }
        }
        __syncthreads();
        // per-row argmax (first-max tie rule)
        if (tid < ROWS) {
            float m = s->lbuf[tid][0];
            int am = 0;
#pragma unroll 8
            for (int vv = 1; vv < VV; vv++) {
                float val = s->lbuf[tid][vv];
                if (val > m) { m = val; am = vv; }
            }
            s->tok[tid] = am;
        }
        __syncthreads();
    }
}

extern "C" void kernel_launch(void* const* d_in, const int* in_sizes, int n_in,
                              void* d_out, int out_size)
{
    const float* z     = (const float*)d_in[0];
    const float* emb   = (const float*)d_in[1];
    const float* z2h_w = (const float*)d_in[2];
    const float* z2h_b = (const float*)d_in[3];
    const float* out_w = (const float*)d_in[4];
    const float* out_b = (const float*)d_in[5];
    const float* wi0 = (const float*)d_in[6];
    const float* wh0 = (const float*)d_in[7];
    const float* bi0 = (const float*)d_in[8];
    const float* bh0 = (const float*)d_in[9];
    const float* wi1 = (const float*)d_in[10];
    const float* wh1 = (const float*)d_in[11];
    const float* bi1 = (const float*)d_in[12];
    const float* bh1 = (const float*)d_in[13];
    const float* wi2 = (const float*)d_in[14];
    const float* wh2 = (const float*)d_in[15];
    const float* bi2 = (const float*)d_in[16];
    const float* bh2 = (const float*)d_in[17];
    float* out = (float*)d_out;

    prep_kernel<<<1536, 256>>>(wi0, wh0, wi1, wh1, wi2, wh2, z2h_w, out_w);

    cudaFuncSetAttribute(moldec_kernel, cudaFuncAttributeMaxDynamicSharedMemorySize,
                         (int)sizeof(SM));
    moldec_kernel<<<NCTAS, NT, sizeof(SM)>>>(
        z, emb, z2h_b, out_b,
        bi0, bh0, bi1, bh1, bi2, bh2,
        out);
}

// round 8
// speedup vs baseline: 1.2739x; 1.2739x over previous
#include <cuda_runtime.h>
#include <cuda_bf16.h>

typedef unsigned long long ull;

#define NCTAS 293         // ceil(4096/14)
#define NT    256
#define ROWS  14          // rows per CTA
#define NPAIR 7           // row pairs per thread
#define RS    16          // padded row stride (floats); slots 14,15 = zero pad
#define HH    256
#define EE    64
#define VV    64
#define ZZ    128
#define TS    119
#define BTOT  4096

// Pre-duplicated weights for packed f32x2 math.
// wrz[k][j] = (w_r,w_r,w_z,w_z) ; wn[k][j] = (w_n,w_n)
// k-slot bases: L0 wi:0(K=64) wh:64 | L1 wi:320 wh:576 | L2 wi:832 wh:1088
__device__ ulonglong2 g_wrz[1344 * 256];
__device__ ull        g_wn [1344 * 256];
__device__ ulonglong2 g_zrz[128 * 256];   // z2h rows (j, 256+j) duplicated
__device__ ull        g_zn [128 * 256];   // z2h row (512+j) duplicated
__device__ float2     g_ow [256 * 64];    // out_w transposed + duplicated: [k][v]

struct SM {
    float hb[3][HH][RS];        // hidden state, k-major       49,152 B
    float xz[ZZ][RS];           // z at init / embedding        8,192 B
    float br[3][HH];            // b_ih_r + b_hh_r
    float bz[3][HH];            // b_ih_z + b_hh_z
    float bin_[3][HH];          // b_ih_n
    float bhn_[3][HH];          // b_hh_n                      12,288 B
    float lbuf[ROWS][VV + 1];   // logits for argmax            3,640 B
    int   tok[ROWS];
};

// ---------------- packed f32x2 helpers ----------------
__device__ __forceinline__ ull dupbits(float f) {
    unsigned u = __float_as_uint(f);
    return ((ull)u << 32) | u;
}
__device__ __forceinline__ ull dup2(float v) {
    ull r; asm("mov.b64 %0, {%1, %1};" : "=l"(r) : "f"(v)); return r;
}
__device__ __forceinline__ void fma2(ull& d, ull a, ull b) {
    asm("fma.rn.f32x2 %0, %1, %2, %0;" : "+l"(d) : "l"(a), "l"(b));
}
__device__ __forceinline__ float f2lo(ull v) { return __uint_as_float((unsigned)(v & 0xffffffffULL)); }
__device__ __forceinline__ float f2hi(ull v) { return __uint_as_float((unsigned)(v >> 32)); }

// ---------------- flag-proof ~1ulp activations ----------------
__device__ __forceinline__ float exp_acc(float x) {
    x = fminf(fmaxf(x, -87.0f), 87.0f);
    float n = rintf(x * 1.4426950408889634f);
    float r = fmaf(n, -6.93145752e-01f, x);
    r = fmaf(n, -1.42860677e-06f, r);
    float p = 1.98412698412e-4f;
    p = fmaf(p, r, 1.38888888889e-3f);
    p = fmaf(p, r, 8.33333333333e-3f);
    p = fmaf(p, r, 4.16666666667e-2f);
    p = fmaf(p, r, 1.66666666667e-1f);
    p = fmaf(p, r, 0.5f);
    p = fmaf(p, r, 1.0f);
    p = fmaf(p, r, 1.0f);
    float sc = __int_as_float(((int)n + 127) << 23);
    return p * sc;
}
__device__ __forceinline__ float sigm(float x) {
    float e = exp_acc(-x);
    return __fdiv_rn(1.0f, 1.0f + e);
}
__device__ __forceinline__ float mytanh(float x) {
    float a = fabsf(x);
    float e = exp_acc(-2.0f * a);
    float r = __fdiv_rn(1.0f - e, 1.0f + e);
    return copysignf(r, x);
}

// ---------------- prep kernel: transpose + duplicate weights ----------------
__global__ void prep_kernel(
    const float* __restrict__ wi0, const float* __restrict__ wh0,
    const float* __restrict__ wi1, const float* __restrict__ wh1,
    const float* __restrict__ wi2, const float* __restrict__ wh2,
    const float* __restrict__ z2h_w, const float* __restrict__ out_w)
{
    int bx = blockIdx.x;
    int j = threadIdx.x;
    if (bx < 1344) {
        const float* W; int ld, kk;
        if      (bx <   64) { W = wi0; ld =  64; kk = bx;        }
        else if (bx <  320) { W = wh0; ld = 256; kk = bx -   64; }
        else if (bx <  576) { W = wi1; ld = 256; kk = bx -  320; }
        else if (bx <  832) { W = wh1; ld = 256; kk = bx -  576; }
        else if (bx < 1088) { W = wi2; ld = 256; kk = bx -  832; }
        else                { W = wh2; ld = 256; kk = bx - 1088; }
        float wr = W[(size_t)j * ld + kk];
        float wz = W[(size_t)(256 + j) * ld + kk];
        float wn = W[(size_t)(512 + j) * ld + kk];
        ulonglong2 e; e.x = dupbits(wr); e.y = dupbits(wz);
        g_wrz[bx * 256 + j] = e;
        g_wn [bx * 256 + j] = dupbits(wn);
    } else if (bx < 1472) {
        int kz = bx - 1344;
        float a = z2h_w[(size_t)j * ZZ + kz];
        float b = z2h_w[(size_t)(256 + j) * ZZ + kz];
        float c = z2h_w[(size_t)(512 + j) * ZZ + kz];
        ulonglong2 e; e.x = dupbits(a); e.y = dupbits(b);
        g_zrz[kz * 256 + j] = e;
        g_zn [kz * 256 + j] = dupbits(c);
    } else {
        int m = bx - 1472;                 // 0..63
        int id = m * 256 + j;
        int k = id >> 6, v = id & 63;
        float w = out_w[(size_t)v * HH + k];
        g_ow[k * 64 + v] = make_float2(w, w);
    }
}

// ---------------- GEMM phase: thread owns gate j, all 7 row-pairs ----------------
// Direct-indexed loads (no manual rotation) — compiler pipelines & renames.
// acc sections: (0,1,SN) <- (r, z, n)
template<int K, int SN>
__device__ __forceinline__ void gemm_phase(const ulonglong2* __restrict__ wrz,
                                           const ull* __restrict__ wn,
                                           const float* __restrict__ xb,
                                           ull (&acc)[4][NPAIR], int j)
{
    const ulonglong2* wp = wrz + j;
    const ull*        np = wn  + j;
#pragma unroll 2
    for (int k = 0; k < K; k++) {
        ulonglong2 wc = __ldg(wp + (size_t)k * 256);
        ull        nc = __ldg(np + (size_t)k * 256);
        const ulonglong2* xq = (const ulonglong2*)(xb + (size_t)k * RS);
        ulonglong2 xa = xq[0], xb2 = xq[1], xc = xq[2];
        ull x6 = ((const ull*)(xq + 3))[0];
        ull wr = wc.x, wz = wc.y;
        fma2(acc[0][0], wr, xa.x);  fma2(acc[0][1], wr, xa.y);
        fma2(acc[0][2], wr, xb2.x); fma2(acc[0][3], wr, xb2.y);
        fma2(acc[0][4], wr, xc.x);  fma2(acc[0][5], wr, xc.y);
        fma2(acc[0][6], wr, x6);
        fma2(acc[1][0], wz, xa.x);  fma2(acc[1][1], wz, xa.y);
        fma2(acc[1][2], wz, xb2.x); fma2(acc[1][3], wz, xb2.y);
        fma2(acc[1][4], wz, xc.x);  fma2(acc[1][5], wz, xc.y);
        fma2(acc[1][6], wz, x6);
        fma2(acc[SN][0], nc, xa.x);  fma2(acc[SN][1], nc, xa.y);
        fma2(acc[SN][2], nc, xb2.x); fma2(acc[SN][3], nc, xb2.y);
        fma2(acc[SN][4], nc, xc.x);  fma2(acc[SN][5], nc, xc.y);
        fma2(acc[SN][6], nc, x6);
    }
}

// One GRU layer step for layer l (single-buffer, in-place update).
template<int KIN>
__device__ __forceinline__ void layer_stepB(SM* s, const float* __restrict__ xb,
                                            const ulonglong2* __restrict__ wrzI,
                                            const ull* __restrict__ wnI,
                                            const ulonglong2* __restrict__ wrzH,
                                            const ull* __restrict__ wnH,
                                            int l, int j)
{
    ull acc[4][NPAIR];
    {
        ull b0 = dup2(s->br[l][j]);
        ull b1 = dup2(s->bz[l][j]);
        ull b2 = dup2(s->bin_[l][j]);
        ull b3 = dup2(s->bhn_[l][j]);
#pragma unroll
        for (int p = 0; p < NPAIR; p++) {
            acc[0][p] = b0; acc[1][p] = b1; acc[2][p] = b2; acc[3][p] = b3;
        }
    }
    gemm_phase<KIN, 2>(wrzI, wnI, xb,               acc, j);   // x @ wi^T -> r, z, inn
    gemm_phase<HH,  3>(wrzH, wnH, &s->hb[l][0][0],  acc, j);   // h @ wh^T -> r, z, hn
    __syncthreads();                        // all reads of hb[l] done
    float* hrow = &s->hb[l][j][0];
#pragma unroll
    for (int p = 0; p < NPAIR; p++) {
        float2 hold = *(const float2*)(hrow + 2 * p);
        float rlo = sigm(f2lo(acc[0][p])), rhi = sigm(f2hi(acc[0][p]));
        float ulo = sigm(f2lo(acc[1][p])), uhi = sigm(f2hi(acc[1][p]));
        float nlo = mytanh(f2lo(acc[2][p]) + rlo * f2lo(acc[3][p]));
        float nhi = mytanh(f2hi(acc[2][p]) + rhi * f2hi(acc[3][p]));
        float2 hnew;
        hnew.x = (1.0f - ulo) * nlo + ulo * hold.x;
        hnew.y = (1.0f - uhi) * nhi + uhi * hold.y;
        *(float2*)(hrow + 2 * p) = hnew;
    }
    __syncthreads();                        // new hb[l] visible
}

__global__ void __launch_bounds__(NT, 2) moldec_kernel(
    const float* __restrict__ z,     const float* __restrict__ emb,
    const float* __restrict__ z2h_b, const float* __restrict__ out_b,
    const float* __restrict__ bi0, const float* __restrict__ bh0,
    const float* __restrict__ bi1, const float* __restrict__ bh1,
    const float* __restrict__ bi2, const float* __restrict__ bh2,
    float* __restrict__ out)
{
    extern __shared__ char smraw[];
    SM* s = (SM*)smraw;
    const int tid = threadIdx.x;
    const int row0 = blockIdx.x * ROWS;
    const int j = tid;             // gate index (256 threads, one j each)

    // combined biases to smem
    {
        const float* bip[3] = {bi0, bi1, bi2};
        const float* bhp[3] = {bh0, bh1, bh2};
#pragma unroll
        for (int l = 0; l < 3; l++) {
            s->br[l][j]   = bip[l][j]          + bhp[l][j];
            s->bz[l][j]   = bip[l][HH + j]     + bhp[l][HH + j];
            s->bin_[l][j] = bip[l][2 * HH + j];
            s->bhn_[l][j] = bhp[l][2 * HH + j];
        }
    }
    // zero pad slots 14,15 of every k-row (hb + xz) once; they stay zero forever
    for (int i = tid; i < 3 * HH + ZZ; i += NT) {
        float* rowp = (i < 3 * HH) ? &s->hb[i >> 8][i & 255][0] : &s->xz[i - 3 * HH][0];
        rowp[14] = 0.0f; rowp[15] = 0.0f;
    }
    // stage z transposed (k-major), zero-fill invalid rows
    for (int i = tid; i < ZZ * ROWS; i += NT) {
        int r = i >> 7, k = i & 127;
        int grow = row0 + r;
        s->xz[k][r] = (grow < BTOT) ? z[(size_t)grow * ZZ + k] : 0.0f;
    }
    if (tid < ROWS) s->tok[tid] = 1;
    __syncthreads();

    // initial hidden: h0[l] = tanh(z @ z2h_w^T + z2h_b)
    {
        ull acc[4][NPAIR];
#pragma unroll
        for (int ss = 0; ss < 3; ss++) {
            ull b = dup2(z2h_b[ss * 256 + j]);
#pragma unroll
            for (int p = 0; p < NPAIR; p++) acc[ss][p] = b;
        }
#pragma unroll
        for (int p = 0; p < NPAIR; p++) acc[3][p] = 0ULL;
        gemm_phase<ZZ, 2>(g_zrz, g_zn, &s->xz[0][0], acc, j);
#pragma unroll
        for (int ss = 0; ss < 3; ss++) {
            float* hrow = &s->hb[ss][j][0];
#pragma unroll
            for (int p = 0; p < NPAIR; p++) {
                float2 hv;
                hv.x = mytanh(f2lo(acc[ss][p]));
                hv.y = mytanh(f2hi(acc[ss][p]));
                *(float2*)(hrow + 2 * p) = hv;
            }
        }
        __syncthreads();
    }

    const ulonglong2* wrzi0 = g_wrz;              const ull* wni0 = g_wn;
    const ulonglong2* wrzh0 = g_wrz +   64 * 256; const ull* wnh0 = g_wn +   64 * 256;
    const ulonglong2* wrzi1 = g_wrz +  320 * 256; const ull* wni1 = g_wn +  320 * 256;
    const ulonglong2* wrzh1 = g_wrz +  576 * 256; const ull* wnh1 = g_wn +  576 * 256;
    const ulonglong2* wrzi2 = g_wrz +  832 * 256; const ull* wni2 = g_wn +  832 * 256;
    const ulonglong2* wrzh2 = g_wrz + 1088 * 256; const ull* wnh2 = g_wn + 1088 * 256;

    // out-proj thread mapping: v = vocab idx, g = row group (pairs 2g, 2g+1)
    const int v = tid & 63;
    const int g = tid >> 6;            // 0..3
    const int so0 = g * 4;             // float offset of pair 2g
    const int so1 = g * 4 + 2;         // float offset of pair 2g+1 (g=3: zero pad)
    const float ob = out_b[v];

    // decode loop
    for (int t = 0; t < TS; t++) {
        // embedding gather into xz (k-major)
        for (int i = tid; i < EE * ROWS; i += NT) {
            int r = i >> 6, k = i & 63;
            s->xz[k][r] = emb[(size_t)s->tok[r] * EE + k];
        }
        __syncthreads();

        layer_stepB<EE>(s, &s->xz[0][0],    wrzi0, wni0, wrzh0, wnh0, 0, j);
        layer_stepB<HH>(s, &s->hb[0][0][0], wrzi1, wni1, wrzh1, wnh1, 1, j);
        layer_stepB<HH>(s, &s->hb[1][0][0], wrzi2, wni2, wrzh2, wnh2, 2, j);

        // output projection: logits = hb[2] @ out_w^T + out_b
        {
            ull o0 = dup2(ob);
            ull o1 = o0;
            const float* xs = &s->hb[2][0][0];
            const ull* owp = (const ull*)g_ow;
            for (int kb = 0; kb < HH; kb += 8) {
                ull wreg[8];
#pragma unroll
                for (int i = 0; i < 8; i++) wreg[i] = owp[(kb + i) * 64 + v];
#pragma unroll
                for (int i = 0; i < 8; i++) {
                    const float* xrow = xs + (size_t)(kb + i) * RS;
                    fma2(o0, wreg[i], *(const ull*)(xrow + so0));
                    fma2(o1, wreg[i], *(const ull*)(xrow + so1));
                }
            }
            {
                int r0 = g * 4;
                float l0 = f2lo(o0), l1 = f2hi(o0), l2 = f2lo(o1), l3 = f2hi(o1);
                s->lbuf[r0 + 0][v] = l0;
                s->lbuf[r0 + 1][v] = l1;
                if (r0 + 2 < ROWS) {       // g=3 second pair is padding
                    s->lbuf[r0 + 2][v] = l2;
                    s->lbuf[r0 + 3][v] = l3;
                }
                if (row0 + r0 + 0 < BTOT) out[((size_t)(row0 + r0 + 0) * TS + t) * VV + v] = l0;
                if (row0 + r0 + 1 < BTOT) out[((size_t)(row0 + r0 + 1) * TS + t) * VV + v] = l1;
                if (r0 + 2 < ROWS) {
                    if (row0 + r0 + 2 < BTOT) out[((size_t)(row0 + r0 + 2) * TS + t) * VV + v] = l2;
                    if (row0 + r0 + 3 < BTOT) out[((size_t)(row0 + r0 + 3) * TS + t) * VV + v] = l3;
                }
            }
        }
        __syncthreads();
        // per-row argmax (first-max tie rule)
        if (tid < ROWS) {
            float m = s->lbuf[tid][0];
            int am = 0;
#pragma unroll 8
            for (int vv = 1; vv < VV; vv++) {
                float val = s->lbuf[tid][vv];
                if (val > m) { m = val; am = vv; }
            }
            s->tok[tid] = am;
        }
        __syncthreads();
    }
}

extern "C" void kernel_launch(void* const* d_in, const int* in_sizes, int n_in,
                              void* d_out, int out_size)
{
    const float* z     = (const float*)d_in[0];
    const float* emb   = (const float*)d_in[1];
    const float* z2h_w = (const float*)d_in[2];
    const float* z2h_b = (const float*)d_in[3];
    const float* out_w = (const float*)d_in[4];
    const float* out_b = (const float*)d_in[5];
    const float* wi0 = (const float*)d_in[6];
    const float* wh0 = (const float*)d_in[7];
    const float* bi0 = (const float*)d_in[8];
    const float* bh0 = (const float*)d_in[9];
    const float* wi1 = (const float*)d_in[10];
    const float* wh1 = (const float*)d_in[11];
    const float* bi1 = (const float*)d_in[12];
    const float* bh1 = (const float*)d_in[13];
    const float* wi2 = (const float*)d_in[14];
    const float* wh2 = (const float*)d_in[15];
    const float* bi2 = (const float*)d_in[16];
    const float* bh2 = (const float*)d_in[17];
    float* out = (float*)d_out;

    prep_kernel<<<1536, 256>>>(wi0, wh0, wi1, wh1, wi2, wh2, z2h_w, out_w);

    cudaFuncSetAttribute(moldec_kernel, cudaFuncAttributeMaxDynamicSharedMemorySize,
                         (int)sizeof(SM));
    moldec_kernel<<<NCTAS, NT, sizeof(SM)>>>(
        z, emb, z2h_b, out_b,
        bi0, bh0, bi1, bh1, bi2, bh2,
        out);
}